// round 7
// baseline (speedup 1.0000x reference)
#include <cuda_runtime.h>
#include <cuda_bf16.h>

// PowerSpectrum: out[n, l*512 + q*16 + p] = cg[l] * sum_m x_nu[l,n,m,q] * x_1[l,n,m,p]
// L=4, M=7, F_NU=32, F_1=16.
//
// Round-7: NO shared memory, NO syncs. Direct sector-perfect global loads:
//   a[m][k]: lane j loads word m*32 + (j>>2) + 8k  -> 8 consecutive words/warp
//            = exactly one 32B sector per LDG.32 (4-way lane merge); 28 loads
//            cover the 28 x_nu sectors of the tile exactly once.
//   b[m]:    lane j loads float4 m*4 + (j&3)       -> 64B/warp = 2 sectors per
//            LDG.128 (8-way merge); 7 loads cover the 14 x_1 sectors once.
// Unrolled loop gives ptxas a deep independent-load window (MLP ~16), so DRAM
// latency is hidden inside each warp without staging. Store mapping unchanged:
// lane j owns p-quad (j&3)*4, q=(j>>2)+8k -> every STG.128 is contiguous 512B.

#define PS_L  4
#define PS_M  7
#define PS_FN 32
#define PS_FP 16
#define OUT_PER_N (PS_L * PS_FN * PS_FP)   // 2048

__global__ __launch_bounds__(256)
void ps_kernel(const float* __restrict__ x_nu,
               const float* __restrict__ x_1,
               float* __restrict__ out,
               int N)
{
    const int t = threadIdx.x;
    const int w = t >> 5;                  // warp 0..7
    const int j = t & 31;                  // lane
    const int s = w >> 2;                  // sample slot 0..1
    const int l = w & 3;                   // angular channel
    const int n = blockIdx.x * 2 + s;

    const int qb = j >> 2;                 // q base 0..7 (q = qb + 8k)
    const int pq = j & 3;                  // p-quad (p = pq*4 .. pq*4+3)

    // a: x_nu tile base (floats), offset by qb
    const float* an = x_nu + ((size_t)l * N + n) * (PS_M * PS_FN) + qb;
    // b: x_1 tile base (float4), offset by pq
    const float4* bp = reinterpret_cast<const float4*>(
                           x_1 + ((size_t)l * N + n) * (PS_M * PS_FP)) + pq;

    float4 acc0 = make_float4(0.f, 0.f, 0.f, 0.f);
    float4 acc1 = acc0, acc2 = acc0, acc3 = acc0;

#pragma unroll
    for (int m = 0; m < PS_M; m++) {
        const float4 b = __ldg(bp + m * 4);
        const float a0 = __ldg(an + m * PS_FN +  0);
        const float a1 = __ldg(an + m * PS_FN +  8);
        const float a2 = __ldg(an + m * PS_FN + 16);
        const float a3 = __ldg(an + m * PS_FN + 24);

        acc0.x = fmaf(a0, b.x, acc0.x);
        acc0.y = fmaf(a0, b.y, acc0.y);
        acc0.z = fmaf(a0, b.z, acc0.z);
        acc0.w = fmaf(a0, b.w, acc0.w);
        acc1.x = fmaf(a1, b.x, acc1.x);
        acc1.y = fmaf(a1, b.y, acc1.y);
        acc1.z = fmaf(a1, b.z, acc1.z);
        acc1.w = fmaf(a1, b.w, acc1.w);
        acc2.x = fmaf(a2, b.x, acc2.x);
        acc2.y = fmaf(a2, b.y, acc2.y);
        acc2.z = fmaf(a2, b.z, acc2.z);
        acc2.w = fmaf(a2, b.w, acc2.w);
        acc3.x = fmaf(a3, b.x, acc3.x);
        acc3.y = fmaf(a3, b.y, acc3.y);
        acc3.z = fmaf(a3, b.z, acc3.z);
        acc3.w = fmaf(a3, b.w, acc3.w);
    }

    const float cgs[PS_L] = {1.0f, 0.57735026918962576f,
                             0.44721359549995794f, 0.37796447300922722f};
    const float cg = cgs[l];

    acc0.x *= cg; acc0.y *= cg; acc0.z *= cg; acc0.w *= cg;
    acc1.x *= cg; acc1.y *= cg; acc1.z *= cg; acc1.w *= cg;
    acc2.x *= cg; acc2.y *= cg; acc2.z *= cg; acc2.w *= cg;
    acc3.x *= cg; acc3.y *= cg; acc3.z *= cg; acc3.w *= cg;

    // float4 index within (n,l) block = j + 32k -> contiguous 512B per STG
    float4* o = reinterpret_cast<float4*>(
        out + (size_t)n * OUT_PER_N + l * (PS_FN * PS_FP));
    o[j +  0] = acc0;
    o[j + 32] = acc1;
    o[j + 64] = acc2;
    o[j + 96] = acc3;
}

extern "C" void kernel_launch(void* const* d_in, const int* in_sizes, int n_in,
                              void* d_out, int out_size)
{
    const float* x_nu = (const float*)d_in[0];
    const float* x_1  = (const float*)d_in[1];
    float* out = (float*)d_out;

    const int N = in_sizes[0] / (PS_L * PS_M * PS_FN);

    ps_kernel<<<N / 2, 256>>>(x_nu, x_1, out, N);
}

// round 8
// speedup vs baseline: 1.1907x; 1.1907x over previous
#include <cuda_runtime.h>
#include <cuda_bf16.h>

// PowerSpectrum: out[n, l*512 + q*16 + p] = cg[l] * sum_m x_nu[l,n,m,q] * x_1[l,n,m,p]
// L=4, M=7, F_NU=32, F_1=16.
//
// Round-8: persistent warps + REGISTER prefetch (no cp.async, single smem buf).
// CTA = 4 warps (128 thr), warp w owns l=w and the n-chain blockIdx.x (stride
// gridDim.x). Loop: STS current tile -> syncwarp -> LDG next tile into the SAME
// regs (already consumed by STS) -> compute from smem -> STG. The prefetch LDGs
// get a full tile of compute to land, so no warp ever waits a DRAM latency.
// Compute/store mapping = R4: lane j owns p-quad (j&3)*4, q=(j>>2)+8k -> every
// STG.128 is contiguous 512B.

#define PS_L  4
#define PS_M  7
#define PS_FN 32
#define PS_FP 16
#define OUT_PER_N (PS_L * PS_FN * PS_FP)   // 2048
#define F4_PER_TILE 84                     // 56 (x_nu) + 28 (x_1)
#define NSM 148
#define CTAS_PER_SM 10

__global__ __launch_bounds__(128, CTAS_PER_SM)
void ps_kernel(const float* __restrict__ x_nu,
               const float* __restrict__ x_1,
               float* __restrict__ out,
               int N)
{
    __shared__ float4 sm[4 * F4_PER_TILE]; // warp-private tiles

    const int t = threadIdx.x;
    const int w = t >> 5;                  // warp 0..3 -> l
    const int j = t & 31;                  // lane
    const int l = w;

    const int chain  = blockIdx.x;
    const int stride = gridDim.x;
    if (chain >= N) return;

    const int qb = j >> 2;                 // q = qb + 8k
    const int pq = j & 3;                  // p = pq*4 .. pq*4+3

    const float4* gx = reinterpret_cast<const float4*>(x_nu) +
                       ((size_t)l * N + chain) * 56;
    const float4* g1 = reinterpret_cast<const float4*>(x_1) +
                       ((size_t)l * N + chain) * 28;
    float4* smw = sm + w * F4_PER_TILE;

    const float cgs[PS_L] = {1.0f, 0.57735026918962576f,
                             0.44721359549995794f, 0.37796447300922722f};
    const float cg = cgs[l];

    const long gx_step = (long)stride * 56;
    const long g1_step = (long)stride * 28;

    // ---- prologue: load first tile into registers ----
    float4 v0 = gx[j];
    float4 v1 = (j < 24) ? gx[32 + j] : g1[j - 24];
    float4 v2 = make_float4(0.f, 0.f, 0.f, 0.f);
    if (j < 20) v2 = g1[8 + j];

    for (int n = chain; n < N; n += stride) {
        // stage current tile
        smw[j]      = v0;
        smw[32 + j] = v1;
        if (j < 20) smw[64 + j] = v2;
        __syncwarp();

        // prefetch next tile into the same registers (independent of compute)
        gx += gx_step;
        g1 += g1_step;
        if (n + stride < N) {
            v0 = gx[j];
            v1 = (j < 24) ? gx[32 + j] : g1[j - 24];
            if (j < 20) v2 = g1[8 + j];
        }

        // compute current tile from smem
        const float*  an = reinterpret_cast<const float*>(smw);   // [m*32 + q]
        const float4* bp = smw + 56 + pq;                         // [m*4 + pq]

        float4 acc0 = make_float4(0.f, 0.f, 0.f, 0.f);
        float4 acc1 = acc0, acc2 = acc0, acc3 = acc0;

#pragma unroll
        for (int m = 0; m < PS_M; m++) {
            const float4 b = bp[m * 4];
            const float a0 = an[m * PS_FN + qb +  0];
            const float a1 = an[m * PS_FN + qb +  8];
            const float a2 = an[m * PS_FN + qb + 16];
            const float a3 = an[m * PS_FN + qb + 24];

            acc0.x = fmaf(a0, b.x, acc0.x);
            acc0.y = fmaf(a0, b.y, acc0.y);
            acc0.z = fmaf(a0, b.z, acc0.z);
            acc0.w = fmaf(a0, b.w, acc0.w);
            acc1.x = fmaf(a1, b.x, acc1.x);
            acc1.y = fmaf(a1, b.y, acc1.y);
            acc1.z = fmaf(a1, b.z, acc1.z);
            acc1.w = fmaf(a1, b.w, acc1.w);
            acc2.x = fmaf(a2, b.x, acc2.x);
            acc2.y = fmaf(a2, b.y, acc2.y);
            acc2.z = fmaf(a2, b.z, acc2.z);
            acc2.w = fmaf(a2, b.w, acc2.w);
            acc3.x = fmaf(a3, b.x, acc3.x);
            acc3.y = fmaf(a3, b.y, acc3.y);
            acc3.z = fmaf(a3, b.z, acc3.z);
            acc3.w = fmaf(a3, b.w, acc3.w);
        }

        acc0.x *= cg; acc0.y *= cg; acc0.z *= cg; acc0.w *= cg;
        acc1.x *= cg; acc1.y *= cg; acc1.z *= cg; acc1.w *= cg;
        acc2.x *= cg; acc2.y *= cg; acc2.z *= cg; acc2.w *= cg;
        acc3.x *= cg; acc3.y *= cg; acc3.z *= cg; acc3.w *= cg;

        float4* o = reinterpret_cast<float4*>(
            out + (size_t)n * OUT_PER_N + l * (PS_FN * PS_FP));
        o[j +  0] = acc0;
        o[j + 32] = acc1;
        o[j + 64] = acc2;
        o[j + 96] = acc3;

        // next iteration's STS waits (via scoreboard) only on v0..v2
        __syncwarp();
    }
}

extern "C" void kernel_launch(void* const* d_in, const int* in_sizes, int n_in,
                              void* d_out, int out_size)
{
    const float* x_nu = (const float*)d_in[0];
    const float* x_1  = (const float*)d_in[1];
    float* out = (float*)d_out;

    const int N = in_sizes[0] / (PS_L * PS_M * PS_FN);

    int grid = NSM * CTAS_PER_SM;          // one resident persistent wave
    if (grid > N) grid = N;

    ps_kernel<<<grid, 128>>>(x_nu, x_1, out, N);
}

// round 9
// speedup vs baseline: 1.4380x; 1.2077x over previous
#include <cuda_runtime.h>
#include <cuda_bf16.h>

// PowerSpectrum: out[n, l*512 + q*16 + p] = cg[l] * sum_m x_nu[l,n,m,q] * x_1[l,n,m,p]
// L=4, M=7, F_NU=32, F_1=16.
//
// Round-9: R4 dataflow with 2 n-tiles batched per warp iteration.
// Warp w owns l=w and samples {2b, 2b+1}. It issues all 6 independent LDG.128
// (both tiles), STSs them immediately (staging regs die at once — no persistent
// prefetch registers, unlike R8), one __syncwarp, then computes+stores tile A
// then tile B. Doubles the in-flight DRAM requests per warp vs R4 while keeping
// the structure register-lean. Store mapping per tile: lane j owns p-quad
// (j&3)*4, q=(j>>2)+8k -> every STG.128 contiguous 512B.

#define PS_L  4
#define PS_M  7
#define PS_FN 32
#define PS_FP 16
#define OUT_PER_N (PS_L * PS_FN * PS_FP)   // 2048
#define F4_PER_TILE 84                     // 56 (x_nu) + 28 (x_1)

__global__ __launch_bounds__(128, 12)
void ps_kernel(const float* __restrict__ x_nu,
               const float* __restrict__ x_1,
               float* __restrict__ out,
               int N)
{
    // per-warp: 2 tiles
    __shared__ float4 sm[4 * 2 * F4_PER_TILE];

    const int t = threadIdx.x;
    const int w = t >> 5;                  // warp 0..3 -> l
    const int j = t & 31;                  // lane
    const int l = w;
    const int n0 = blockIdx.x * 2;         // samples n0, n0+1

    const float4* gxA = reinterpret_cast<const float4*>(x_nu) + ((size_t)l * N + n0) * 56;
    const float4* g1A = reinterpret_cast<const float4*>(x_1)  + ((size_t)l * N + n0) * 28;
    const float4* gxB = gxA + 56;
    const float4* g1B = g1A + 28;

    float4* smA = sm + (w * 2 + 0) * F4_PER_TILE;
    float4* smB = sm + (w * 2 + 1) * F4_PER_TILE;

    // ---- issue all 6 independent LDGs, STS each immediately ----
    {
        const float4 a0 = gxA[j];
        const float4 a1 = (j < 24) ? gxA[32 + j] : g1A[j - 24];
        float4 a2; if (j < 20) a2 = g1A[8 + j];
        const float4 b0 = gxB[j];
        const float4 b1 = (j < 24) ? gxB[32 + j] : g1B[j - 24];
        float4 b2; if (j < 20) b2 = g1B[8 + j];

        smA[j]      = a0;
        smA[32 + j] = a1;
        if (j < 20) smA[64 + j] = a2;
        smB[j]      = b0;
        smB[32 + j] = b1;
        if (j < 20) smB[64 + j] = b2;
    }
    __syncwarp();

    const int qb = j >> 2;                 // q = qb + 8k
    const int pq = j & 3;                  // p = pq*4 .. pq*4+3
    const float cgs[PS_L] = {1.0f, 0.57735026918962576f,
                             0.44721359549995794f, 0.37796447300922722f};
    const float cg = cgs[l];

#pragma unroll
    for (int s = 0; s < 2; s++) {
        const float4* smw = (s == 0) ? smA : smB;
        const float*  an  = reinterpret_cast<const float*>(smw);   // [m*32 + q]
        const float4* bp  = smw + 56 + pq;                         // [m*4 + pq]

        float4 acc0 = make_float4(0.f, 0.f, 0.f, 0.f);
        float4 acc1 = acc0, acc2 = acc0, acc3 = acc0;

#pragma unroll
        for (int m = 0; m < PS_M; m++) {
            const float4 b = bp[m * 4];
            const float a0 = an[m * PS_FN + qb +  0];
            const float a1 = an[m * PS_FN + qb +  8];
            const float a2 = an[m * PS_FN + qb + 16];
            const float a3 = an[m * PS_FN + qb + 24];

            acc0.x = fmaf(a0, b.x, acc0.x);
            acc0.y = fmaf(a0, b.y, acc0.y);
            acc0.z = fmaf(a0, b.z, acc0.z);
            acc0.w = fmaf(a0, b.w, acc0.w);
            acc1.x = fmaf(a1, b.x, acc1.x);
            acc1.y = fmaf(a1, b.y, acc1.y);
            acc1.z = fmaf(a1, b.z, acc1.z);
            acc1.w = fmaf(a1, b.w, acc1.w);
            acc2.x = fmaf(a2, b.x, acc2.x);
            acc2.y = fmaf(a2, b.y, acc2.y);
            acc2.z = fmaf(a2, b.z, acc2.z);
            acc2.w = fmaf(a2, b.w, acc2.w);
            acc3.x = fmaf(a3, b.x, acc3.x);
            acc3.y = fmaf(a3, b.y, acc3.y);
            acc3.z = fmaf(a3, b.z, acc3.z);
            acc3.w = fmaf(a3, b.w, acc3.w);
        }

        acc0.x *= cg; acc0.y *= cg; acc0.z *= cg; acc0.w *= cg;
        acc1.x *= cg; acc1.y *= cg; acc1.z *= cg; acc1.w *= cg;
        acc2.x *= cg; acc2.y *= cg; acc2.z *= cg; acc2.w *= cg;
        acc3.x *= cg; acc3.y *= cg; acc3.z *= cg; acc3.w *= cg;

        float4* o = reinterpret_cast<float4*>(
            out + (size_t)(n0 + s) * OUT_PER_N + l * (PS_FN * PS_FP));
        o[j +  0] = acc0;
        o[j + 32] = acc1;
        o[j + 64] = acc2;
        o[j + 96] = acc3;
    }
}

extern "C" void kernel_launch(void* const* d_in, const int* in_sizes, int n_in,
                              void* d_out, int out_size)
{
    const float* x_nu = (const float*)d_in[0];
    const float* x_1  = (const float*)d_in[1];
    float* out = (float*)d_out;

    const int N = in_sizes[0] / (PS_L * PS_M * PS_FN);

    ps_kernel<<<N / 2, 128>>>(x_nu, x_1, out, N);
}